// round 6
// baseline (speedup 1.0000x reference)
#include <cuda_runtime.h>
#include <float.h>

// Problem constants
#define BATCHES 16
#define NB 8192
#define M 1024
#define KNN 16

// FPS kernel config
#define FPS_THR 512
#define PPT (NB / FPS_THR)        // 16 points per thread
#define PAIRS (PPT / 2)           // 8 f32x2 pairs per thread
#define FPS_WARPS (FPS_THR / 32)  // 16

// KNN kernel config: one lane per centroid, 128 centroids per block
#define KNN_THR 128
#define KNN_BLKS_PER_BATCH (M / KNN_THR)  // 8

typedef unsigned long long u64;

// ---- f32x2 packed helpers (sm_103a; halves are exact independent rn ops) ----
__device__ __forceinline__ u64 pk2(float lo, float hi) {
    u64 r;
    asm("mov.b64 %0, {%1, %2};" : "=l"(r) : "f"(lo), "f"(hi));
    return r;
}
__device__ __forceinline__ void upk2(u64 v, float& lo, float& hi) {
    asm("mov.b64 {%0, %1}, %2;" : "=f"(lo), "=f"(hi) : "l"(v));
}
__device__ __forceinline__ u64 add2(u64 a, u64 b) {
    u64 d;
    asm("add.rn.f32x2 %0, %1, %2;" : "=l"(d) : "l"(a), "l"(b));
    return d;
}
__device__ __forceinline__ u64 mul2(u64 a, u64 b) {
    u64 d;
    asm("mul.rn.f32x2 %0, %1, %2;" : "=l"(d) : "l"(a), "l"(b));
    return d;
}
__device__ __forceinline__ u64 fma2(u64 a, u64 b, u64 c) {
    u64 d;
    asm("fma.rn.f32x2 %0, %1, %2, %3;" : "=l"(d) : "l"(a), "l"(b), "l"(c));
    return d;
}

// ---------------------------------------------------------------------------
// FPS: one block per batch. Points live in registers, packed 2-wide (f32x2).
// Per step (2 barriers):
//   epoch 1: packed min_d2 update (bit-exact vs scalar: each half is the same
//            rn sequence dx=px+(-cx); fma(dz,dz,fma(dy,dy,dx*dx))), warp
//            redux.max.u32 on float bits (m >= 0 so uint order == float
//            order), lane0 writes swarp[wid].                    -- barrier A
//   epoch 2: ALL warps redundantly redux over swarp[0..15] -> gmax; owners
//            rescan m for bits==gmax and atomicMin their global index into
//            swin[s&1] (lowest index wins == jnp.argmax first-max); tid0
//            resets swin[1-(s&1)] for the NEXT step (its last read was
//            before barrier A; next write is after the next barrier A --
//            race-free).                                          -- barrier B
//   read widx = swin[s&1].
// idx[0] = 0. Selection chain bit-exact vs R1-verified scalar form.
// ---------------------------------------------------------------------------
__global__ __launch_bounds__(FPS_THR, 1)
void fps_kernel(const float* __restrict__ pos, float* __restrict__ out) {
    extern __shared__ float sh[];
    float* sx = sh;
    float* sy = sh + NB;
    float* sz = sh + 2 * NB;
    __shared__ unsigned swarp[FPS_WARPS];
    __shared__ int swin[2];

    const int b = blockIdx.x;
    const int tid = threadIdx.x;
    const int lane = tid & 31;
    const int wid = tid >> 5;
    const int gbase = b * NB;

    // stage batch points into shared (SoA) for centroid broadcast lookups
    for (int i = tid; i < NB; i += FPS_THR) {
        const float* p = pos + (size_t)(gbase + i) * 3;
        sx[i] = p[0];
        sy[i] = p[1];
        sz[i] = p[2];
    }
    if (tid == 0) {
        swin[0] = 0x7fffffff;
        swin[1] = 0x7fffffff;
    }
    __syncthreads();

    // thread-private points packed pairwise + running min distances (scalar)
    u64 px2[PAIRS], py2[PAIRS], pz2[PAIRS];
    float m[PPT];
#pragma unroll
    for (int j = 0; j < PAIRS; j++) {
        int i = tid * PPT + 2 * j;
        px2[j] = pk2(sx[i], sx[i + 1]);
        py2[j] = pk2(sy[i], sy[i + 1]);
        pz2[j] = pk2(sz[i], sz[i + 1]);
        m[2 * j] = FLT_MAX;
        m[2 * j + 1] = FLT_MAX;
    }

    int widx = 0;  // idx[0] = 0 (deterministic start)
    for (int s = 0; s < M; s++) {
        const float cx = sx[widx], cy = sy[widx], cz = sz[widx];
        if (tid == 0) {
            float* o = out + ((size_t)b * M + s) * 3;
            o[0] = cx;
            o[1] = cy;
            o[2] = cz;
        }
        if (s == M - 1) break;
        const int par = s & 1;

        // broadcast negated centroid, packed (negation is exact)
        const u64 ncx = pk2(-cx, -cx);
        const u64 ncy = pk2(-cy, -cy);
        const u64 ncz = pk2(-cz, -cz);

        // packed min_d2 update; track thread-local max
        float tmax = -FLT_MAX;
#pragma unroll
        for (int j = 0; j < PAIRS; j++) {
            u64 dx = add2(px2[j], ncx);     // == px - cx per half
            u64 dy = add2(py2[j], ncy);
            u64 dz = add2(pz2[j], ncz);
            u64 t = mul2(dx, dx);           // dx*dx
            t = fma2(dy, dy, t);            // fma(dy,dy,.)
            t = fma2(dz, dz, t);            // fma(dz,dz,.)
            float d2a, d2b;
            upk2(t, d2a, d2b);              // register aliasing, free
            float ma = fminf(m[2 * j], d2a);
            float mb = fminf(m[2 * j + 1], d2b);
            m[2 * j] = ma;
            m[2 * j + 1] = mb;
            tmax = fmaxf(tmax, ma);
            tmax = fmaxf(tmax, mb);
        }

        // warp max on float bits (m >= 0 -> uint order == float order)
        const unsigned tbits = __float_as_uint(tmax);
        const unsigned wbits = __reduce_max_sync(0xffffffffu, tbits);
        if (lane == 0) swarp[wid] = wbits;
        __syncthreads();  // barrier A

        // all warps redundantly compute the block max (no second barrier hop)
        unsigned v = (lane < FPS_WARPS) ? swarp[lane] : 0u;
        const unsigned g = __reduce_max_sync(0xffffffffu, v);

        // owners rescan; lowest global index wins ties (== jnp.argmax)
        if (tbits == g) {
#pragma unroll
            for (int j = 0; j < PPT; j++)
                if (__float_as_uint(m[j]) == g)
                    atomicMin(&swin[par], tid * PPT + j);
        }
        // reset the OTHER buffer for next step (safe: last read of it was
        // before barrier A this step; next write is after next barrier A)
        if (tid == 0) swin[1 - par] = 0x7fffffff;
        __syncthreads();  // barrier B
        widx = swin[par];
    }
}

// ---------------------------------------------------------------------------
// KNN: one lane per centroid; warp broadcast-reads every point from shared.
// d2 replicates the reference's XLA arithmetic EXACTLY:
//   pn, cn: square-and-reduce with plain mul/add (NO fma — XLA doesn't
//           contract elementwise code)
//   dot:    ascending-k fma chain  fma(c2,p2, fma(c1,p1, rn(c0*p0)))
//   d2:     rn(cn - 2*dot) + pn    (2*dot exact, so fmaf(-2,dot,cn) == sub)
// Point loop unrolled x4 with independent distance chains (one warp/SMSP at
// 128 blocks -> latency must be hidden by ILP). Inserts applied in ascending
// i order -> identical results to the non-unrolled loop.
// Register-resident sorted ascending top-16 with strict-< insertion
// (reproduces lax.top_k ordering incl. lower-index-first ties).
// ---------------------------------------------------------------------------
__global__ __launch_bounds__(KNN_THR, 1)
void knn_kernel(const float* __restrict__ pos, float* __restrict__ out) {
    extern __shared__ float sh[];
    float* sx = sh;
    float* sy = sh + NB;
    float* sz = sh + 2 * NB;
    float* spn = sh + 3 * NB;

    const int bb = blockIdx.x;
    const int b = bb / KNN_BLKS_PER_BATCH;
    const int chunk = bb % KNN_BLKS_PER_BATCH;
    const int tid = threadIdx.x;
    const int gbase = b * NB;

    for (int i = tid; i < NB; i += KNN_THR) {
        const float* p = pos + (size_t)(gbase + i) * 3;
        float xx = p[0], yy = p[1], zz = p[2];
        sx[i] = xx;
        sy[i] = yy;
        sz[i] = zz;
        // |p|^2 with plain mul/add, no contraction (matches XLA emission)
        spn[i] = __fadd_rn(__fadd_rn(__fmul_rn(xx, xx), __fmul_rn(yy, yy)),
                           __fmul_rn(zz, zz));
    }
    __syncthreads();

    const int mloc = chunk * KNN_THR + tid;  // centroid index within batch
    const float* cptr = out + ((size_t)b * M + mloc) * 3;
    const float cx = cptr[0], cy = cptr[1], cz = cptr[2];
    // |c|^2 with plain mul/add, no contraction
    const float cn = __fadd_rn(__fadd_rn(__fmul_rn(cx, cx), __fmul_rn(cy, cy)),
                               __fmul_rn(cz, cz));

    float nd[KNN];
    int ni[KNN];
#pragma unroll
    for (int k = 0; k < KNN; k++) {
        nd[k] = FLT_MAX;
        ni[k] = 0;
    }

#define KNN_D2(i)                                                            \
    __fadd_rn(__fmaf_rn(-2.0f,                                               \
                        __fmaf_rn(cz, sz[i],                                 \
                                  __fmaf_rn(cy, sy[i], __fmul_rn(cx, sx[i]))),\
                        cn),                                                 \
              spn[i])

#define KNN_INSERT(d2v, iv)                                                  \
    if ((d2v) < nd[KNN - 1]) {                                               \
        bool c2 = true;                                                      \
        _Pragma("unroll") for (int k = KNN - 1; k >= 1; k--) {               \
            bool c1 = (d2v) < nd[k - 1];                                     \
            float ndv = c1 ? nd[k - 1] : (c2 ? (d2v) : nd[k]);               \
            int niv = c1 ? ni[k - 1] : (c2 ? (iv) : ni[k]);                  \
            nd[k] = ndv;                                                     \
            ni[k] = niv;                                                     \
            c2 = c1;                                                         \
        }                                                                    \
        if (c2) {                                                            \
            nd[0] = (d2v);                                                   \
            ni[0] = (iv);                                                    \
        }                                                                    \
    }

    for (int i = 0; i < NB; i += 4) {
        // four independent distance chains (ILP hides LDS + fma latency)
        float d0 = KNN_D2(i + 0);
        float d1 = KNN_D2(i + 1);
        float d2 = KNN_D2(i + 2);
        float d3 = KNN_D2(i + 3);
        // inserts in ascending i order -> identical to scalar loop
        KNN_INSERT(d0, i + 0)
        KNN_INSERT(d1, i + 1)
        KNN_INSERT(d2, i + 2)
        KNN_INSERT(d3, i + 3)
    }
#undef KNN_D2
#undef KNN_INSERT

    // groups region starts after centroids; each thread writes 16*3 contiguous
    float* go = out + (size_t)BATCHES * M * 3 + ((size_t)(b * M + mloc)) * KNN * 3;
#pragma unroll
    for (int k = 0; k < KNN; k++) {
        int i = ni[k];
        go[k * 3 + 0] = sx[i];
        go[k * 3 + 1] = sy[i];
        go[k * 3 + 2] = sz[i];
    }
}

// ---------------------------------------------------------------------------
extern "C" void kernel_launch(void* const* d_in, const int* in_sizes, int n_in,
                              void* d_out, int out_size) {
    // metadata order: x (unused), pos, batch (block-constant, implied by i/NB)
    const float* pos = (const float*)d_in[1];
    float* out = (float*)d_out;

    // allow >48KB dynamic shared (idempotent, non-stream API)
    cudaFuncSetAttribute(fps_kernel, cudaFuncAttributeMaxDynamicSharedMemorySize,
                         3 * NB * (int)sizeof(float));
    cudaFuncSetAttribute(knn_kernel, cudaFuncAttributeMaxDynamicSharedMemorySize,
                         4 * NB * (int)sizeof(float));

    fps_kernel<<<BATCHES, FPS_THR, 3 * NB * sizeof(float)>>>(pos, out);
    knn_kernel<<<BATCHES * KNN_BLKS_PER_BATCH, KNN_THR, 4 * NB * sizeof(float)>>>(pos, out);
}

// round 13
// speedup vs baseline: 1.0587x; 1.0587x over previous
#include <cuda_runtime.h>
#include <float.h>

// Problem constants
#define BATCHES 16
#define NB 8192
#define M 1024
#define KNN 16

// FPS kernel config
#define FPS_THR 512
#define PPT (NB / FPS_THR)        // 16 points per thread
#define PAIRS (PPT / 2)           // 8 f32x2 pairs per thread
#define FPS_WARPS (FPS_THR / 32)  // 16

// KNN kernel config: 256 threads; each centroid owned by a lane PAIR
// (two warps scan disjoint halves of the batch, then merge).
#define KNN_THR 256
#define KNN_CPB 128                        // centroids per block
#define KNN_BLKS_PER_BATCH (M / KNN_CPB)   // 8
#define KNN_HALF (NB / 2)                  // 4096 points per half

typedef unsigned long long u64;

// ---- f32x2 packed helpers (sm_103a; halves are exact independent rn ops) ----
__device__ __forceinline__ u64 pk2(float lo, float hi) {
    u64 r;
    asm("mov.b64 %0, {%1, %2};" : "=l"(r) : "f"(lo), "f"(hi));
    return r;
}
__device__ __forceinline__ void upk2u(u64 v, unsigned& lo, unsigned& hi) {
    asm("mov.b64 {%0, %1}, %2;" : "=r"(lo), "=r"(hi) : "l"(v));
}
__device__ __forceinline__ u64 add2(u64 a, u64 b) {
    u64 d;
    asm("add.rn.f32x2 %0, %1, %2;" : "=l"(d) : "l"(a), "l"(b));
    return d;
}
__device__ __forceinline__ u64 mul2(u64 a, u64 b) {
    u64 d;
    asm("mul.rn.f32x2 %0, %1, %2;" : "=l"(d) : "l"(a), "l"(b));
    return d;
}
__device__ __forceinline__ u64 fma2(u64 a, u64 b, u64 c) {
    u64 d;
    asm("fma.rn.f32x2 %0, %1, %2, %3;" : "=l"(d) : "l"(a), "l"(b), "l"(c));
    return d;
}

// ---------------------------------------------------------------------------
// FPS: one block per batch. Points in registers, packed 2-wide (f32x2).
// min_d2 kept as UINT BITS: all d2 >= 0 (sums of non-negative fma terms)
// and init = FLT_MAX bits, so umin/umax on bit patterns == fminf/fmaxf on
// the floats (monotone bijection on [0,inf)) -> IDENTICAL selection, with
// min/max moved to the ALU pipe, off the fma-issue critical path.
// 2 barriers/step; redundant per-warp block redux; double-buffered swin
// with mid-epoch reset; lowest-index tie-break via atomicMin (== jnp.argmax
// first-max). idx[0] = 0. (R6 measured rel_err = 0.0 for this chain.)
// ---------------------------------------------------------------------------
__global__ __launch_bounds__(FPS_THR, 1)
void fps_kernel(const float* __restrict__ pos, float* __restrict__ out) {
    extern __shared__ float sh[];
    float* sx = sh;
    float* sy = sh + NB;
    float* sz = sh + 2 * NB;
    __shared__ unsigned swarp[FPS_WARPS];
    __shared__ int swin[2];

    const int b = blockIdx.x;
    const int tid = threadIdx.x;
    const int lane = tid & 31;
    const int wid = tid >> 5;
    const int gbase = b * NB;

    for (int i = tid; i < NB; i += FPS_THR) {
        const float* p = pos + (size_t)(gbase + i) * 3;
        sx[i] = p[0];
        sy[i] = p[1];
        sz[i] = p[2];
    }
    if (tid == 0) {
        swin[0] = 0x7fffffff;
        swin[1] = 0x7fffffff;
    }
    __syncthreads();

    u64 px2[PAIRS], py2[PAIRS], pz2[PAIRS];
    unsigned m[PPT];
#pragma unroll
    for (int j = 0; j < PAIRS; j++) {
        int i = tid * PPT + 2 * j;
        px2[j] = pk2(sx[i], sx[i + 1]);
        py2[j] = pk2(sy[i], sy[i + 1]);
        pz2[j] = pk2(sz[i], sz[i + 1]);
        m[2 * j] = 0x7f7fffffu;      // FLT_MAX bits
        m[2 * j + 1] = 0x7f7fffffu;
    }

    int widx = 0;  // idx[0] = 0 (deterministic start)
    for (int s = 0; s < M; s++) {
        const float cx = sx[widx], cy = sy[widx], cz = sz[widx];
        if (tid == 0) {
            float* o = out + ((size_t)b * M + s) * 3;
            o[0] = cx;
            o[1] = cy;
            o[2] = cz;
        }
        if (s == M - 1) break;
        const int par = s & 1;

        const u64 ncx = pk2(-cx, -cx);
        const u64 ncy = pk2(-cy, -cy);
        const u64 ncz = pk2(-cz, -cz);

        unsigned tmax = 0u;
#pragma unroll
        for (int j = 0; j < PAIRS; j++) {
            u64 dx = add2(px2[j], ncx);     // == px - cx per half
            u64 dy = add2(py2[j], ncy);
            u64 dz = add2(pz2[j], ncz);
            u64 t = mul2(dx, dx);
            t = fma2(dy, dy, t);
            t = fma2(dz, dz, t);
            unsigned d2a, d2b;
            upk2u(t, d2a, d2b);             // register aliasing, free
            unsigned ma = umin(m[2 * j], d2a);      // == fminf on nonneg
            unsigned mb = umin(m[2 * j + 1], d2b);
            m[2 * j] = ma;
            m[2 * j + 1] = mb;
            tmax = umax(tmax, ma);                  // == fmaxf on nonneg
            tmax = umax(tmax, mb);
        }

        const unsigned wbits = __reduce_max_sync(0xffffffffu, tmax);
        if (lane == 0) swarp[wid] = wbits;
        __syncthreads();  // barrier A

        unsigned v = (lane < FPS_WARPS) ? swarp[lane] : 0u;
        const unsigned g = __reduce_max_sync(0xffffffffu, v);

        if (tmax == g) {
#pragma unroll
            for (int j = 0; j < PPT; j++)
                if (m[j] == g) atomicMin(&swin[par], tid * PPT + j);
        }
        if (tid == 0) swin[1 - par] = 0x7fffffff;
        __syncthreads();  // barrier B
        widx = swin[par];
    }
}

// ---------------------------------------------------------------------------
// KNN, half-split: 256 threads. Warp w (0..7): centroid group cg = w>>1,
// half h = w&1; lane owns centroid c = cg*32+lane and scans points
// [h*4096, h*4096+4096). Each half builds a (d2, idx)-lexicographically
// sorted top-16 (strict-< insert, ascending i => lower index first on
// ties). After sync, the h=0 warp merges the two sorted lists with
// comparator dA<=dB (half-0 indices always lower => == (d,idx)-lex order,
// == lax.top_k semantics). Merge of partial lex-top-16s == full-scan
// top-16 exactly (both lists fully real: 4096 pts >> 16, d2 < FLT_MAX;
// merge reads stay in bounds since a+b = k <= 15).
// Per-point arithmetic replicates XLA emission exactly (R6: rel_err 0.0):
//   pn, cn: square-and-reduce, plain mul/add (no contraction)
//   dot:    fma(cz,z, fma(cy,y, rn(cx*x)))
//   d2:     rn(cn - 2*dot) + pn
// Shared: float4 {x,y,z,|p|^2} per point -> 1x LDS.128 per point.
// ---------------------------------------------------------------------------
__global__ __launch_bounds__(KNN_THR, 1)
void knn_kernel(const float* __restrict__ pos, float* __restrict__ out) {
    extern __shared__ char smem_raw[];
    float4* shp = (float4*)smem_raw;                       // NB*16 = 128KB
    float* sd = (float*)(smem_raw + NB * sizeof(float4));  // 128*32 floats
    int* si = (int*)(sd + KNN_CPB * 2 * KNN);              // 128*32 ints

    const int bb = blockIdx.x;
    const int b = bb / KNN_BLKS_PER_BATCH;
    const int chunk = bb % KNN_BLKS_PER_BATCH;
    const int tid = threadIdx.x;
    const int lane = tid & 31;
    const int w = tid >> 5;
    const int cg = w >> 1;   // centroid group 0..3
    const int h = w & 1;     // half 0/1
    const int gbase = b * NB;

    for (int i = tid; i < NB; i += KNN_THR) {
        const float* p = pos + (size_t)(gbase + i) * 3;
        float xx = p[0], yy = p[1], zz = p[2];
        float pn = __fadd_rn(__fadd_rn(__fmul_rn(xx, xx), __fmul_rn(yy, yy)),
                             __fmul_rn(zz, zz));
        shp[i] = make_float4(xx, yy, zz, pn);
    }
    __syncthreads();

    const int c = cg * 32 + lane;            // centroid within block, 0..127
    const int mloc = chunk * KNN_CPB + c;    // centroid index within batch
    const float* cptr = out + ((size_t)b * M + mloc) * 3;
    const float cx = cptr[0], cy = cptr[1], cz = cptr[2];
    const float cn = __fadd_rn(__fadd_rn(__fmul_rn(cx, cx), __fmul_rn(cy, cy)),
                               __fmul_rn(cz, cz));

    float nd[KNN];
    int ni[KNN];
#pragma unroll
    for (int k = 0; k < KNN; k++) {
        nd[k] = FLT_MAX;
        ni[k] = 0;
    }

#define KNN_D2(P)                                                            \
    __fadd_rn(__fmaf_rn(-2.0f,                                               \
                        __fmaf_rn(cz, (P).z,                                 \
                                  __fmaf_rn(cy, (P).y, __fmul_rn(cx, (P).x))),\
                        cn),                                                 \
              (P).w)

#define KNN_INSERT(d2v, iv)                                                  \
    if ((d2v) < nd[KNN - 1]) {                                               \
        bool c2 = true;                                                      \
        _Pragma("unroll") for (int k = KNN - 1; k >= 1; k--) {               \
            bool c1 = (d2v) < nd[k - 1];                                     \
            float ndv = c1 ? nd[k - 1] : (c2 ? (d2v) : nd[k]);               \
            int niv = c1 ? ni[k - 1] : (c2 ? (iv) : ni[k]);                  \
            nd[k] = ndv;                                                     \
            ni[k] = niv;                                                     \
            c2 = c1;                                                         \
        }                                                                    \
        if (c2) {                                                            \
            nd[0] = (d2v);                                                   \
            ni[0] = (iv);                                                    \
        }                                                                    \
    }

    const int i0 = h * KNN_HALF;
    for (int i = i0; i < i0 + KNN_HALF; i += 4) {
        float4 p0 = shp[i + 0];
        float4 p1 = shp[i + 1];
        float4 p2 = shp[i + 2];
        float4 p3 = shp[i + 3];
        float d0 = KNN_D2(p0);
        float d1 = KNN_D2(p1);
        float d2 = KNN_D2(p2);
        float d3 = KNN_D2(p3);
        KNN_INSERT(d0, i + 0)
        KNN_INSERT(d1, i + 1)
        KNN_INSERT(d2, i + 2)
        KNN_INSERT(d3, i + 3)
    }
#undef KNN_D2
#undef KNN_INSERT

    // stash this half's sorted top-16
    {
        int off = (c * 2 + h) * KNN;
#pragma unroll
        for (int k = 0; k < KNN; k++) {
            sd[off + k] = nd[k];
            si[off + k] = ni[k];
        }
    }
    __syncthreads();

    // h==0 warps merge the two sorted lists (dA<=dB: half-0 index always
    // lower, so <= implements exact (d, idx)-lexicographic preference)
    if (h == 0) {
        const float* dA = sd + (c * 2) * KNN;
        const int* iA = si + (c * 2) * KNN;
        const float* dB = sd + (c * 2 + 1) * KNN;
        const int* iB = si + (c * 2 + 1) * KNN;
        float* go = out + (size_t)BATCHES * M * 3 +
                    ((size_t)(b * M + mloc)) * KNN * 3;
        int a = 0, bcur = 0;
#pragma unroll
        for (int k = 0; k < KNN; k++) {
            float da = dA[a], db = dB[bcur];
            bool takeA = (da <= db);
            int idx = takeA ? iA[a] : iB[bcur];
            a += takeA ? 1 : 0;
            bcur += takeA ? 0 : 1;
            float4 p = shp[idx];
            go[k * 3 + 0] = p.x;
            go[k * 3 + 1] = p.y;
            go[k * 3 + 2] = p.z;
        }
    }
}

// ---------------------------------------------------------------------------
extern "C" void kernel_launch(void* const* d_in, const int* in_sizes, int n_in,
                              void* d_out, int out_size) {
    // metadata order: x (unused), pos, batch (block-constant, implied by i/NB)
    const float* pos = (const float*)d_in[1];
    float* out = (float*)d_out;

    const int knn_smem = NB * (int)sizeof(float4) +
                         KNN_CPB * 2 * KNN * (int)(sizeof(float) + sizeof(int));

    cudaFuncSetAttribute(fps_kernel, cudaFuncAttributeMaxDynamicSharedMemorySize,
                         3 * NB * (int)sizeof(float));
    cudaFuncSetAttribute(knn_kernel, cudaFuncAttributeMaxDynamicSharedMemorySize,
                         knn_smem);

    fps_kernel<<<BATCHES, FPS_THR, 3 * NB * sizeof(float)>>>(pos, out);
    knn_kernel<<<BATCHES * KNN_BLKS_PER_BATCH, KNN_THR, knn_smem>>>(pos, out);
}

// round 14
// speedup vs baseline: 1.1473x; 1.0837x over previous
#include <cuda_runtime.h>
#include <float.h>

// Problem constants
#define BATCHES 16
#define NB 8192
#define M 1024
#define KNN 16

// FPS kernel config
#define FPS_THR 512
#define PPT (NB / FPS_THR)        // 16 points per thread
#define PAIRS (PPT / 2)           // 8 f32x2 pairs per thread
#define FPS_WARPS (FPS_THR / 32)  // 16

// KNN kernel config: 512 threads; warp = (centroid-group, quarter).
#define KNN_THR 512
#define KNN_CPB 128                        // centroids per block
#define KNN_BLKS_PER_BATCH (M / KNN_CPB)   // 8
#define KNN_Q (NB / 4)                     // 2048 points per quarter

typedef unsigned long long u64;

// ---- f32x2 packed helpers (sm_103a; halves are exact independent rn ops) ----
__device__ __forceinline__ u64 pk2(float lo, float hi) {
    u64 r;
    asm("mov.b64 %0, {%1, %2};" : "=l"(r) : "f"(lo), "f"(hi));
    return r;
}
__device__ __forceinline__ void upk2u(u64 v, unsigned& lo, unsigned& hi) {
    asm("mov.b64 {%0, %1}, %2;" : "=r"(lo), "=r"(hi) : "l"(v));
}
__device__ __forceinline__ u64 add2(u64 a, u64 b) {
    u64 d;
    asm("add.rn.f32x2 %0, %1, %2;" : "=l"(d) : "l"(a), "l"(b));
    return d;
}
__device__ __forceinline__ u64 mul2(u64 a, u64 b) {
    u64 d;
    asm("mul.rn.f32x2 %0, %1, %2;" : "=l"(d) : "l"(a), "l"(b));
    return d;
}
__device__ __forceinline__ u64 fma2(u64 a, u64 b, u64 c) {
    u64 d;
    asm("fma.rn.f32x2 %0, %1, %2, %3;" : "=l"(d) : "l"(a), "l"(b), "l"(c));
    return d;
}

// ---------------------------------------------------------------------------
// FPS: one block per batch; ONE barrier per step, atomic-free argmax.
// min_d2 as UINT BITS (d2 >= 0, init FLT_MAX bits: uint order == float
// order). Per step:
//   inner: packed f32x2 distance update (same rn sequence as reference:
//          dx=px+(-cx); fma(dz,dz,fma(dy,dy,dx*dx))), umin/umax on bits.
//   thread: lowest j with m[j]==tmax (reverse scan, j=0 wins) -> gidx.
//   warp:  wmax = redux.max(tmax); cand = (tmax==wmax)?gidx:~0;
//          wmin = redux.min(cand)  -> warp's (max, lowest-owner-index).
//   lane0: store to DOUBLE-BUFFERED swd/swi[s&1][wid].   -- ONE barrier --
//   all warps: same redux pattern over the 16 entries -> (gmax, widx).
// Double-buffer race-freedom: buffer par is read after barrier of step s;
// its next write is in step s+2, after barrier of step s+1, which follows
// every reader's arrival. Tie-break = global lowest index (== jnp.argmax
// first-max). idx[0] = 0. Selected values bit-identical to the R6/R13
// verified chain (integer compares on exact bits).
// ---------------------------------------------------------------------------
__global__ __launch_bounds__(FPS_THR, 1)
void fps_kernel(const float* __restrict__ pos, float* __restrict__ out) {
    extern __shared__ float sh[];
    float* sx = sh;
    float* sy = sh + NB;
    float* sz = sh + 2 * NB;
    __shared__ unsigned swd[2][FPS_WARPS];
    __shared__ unsigned swi[2][FPS_WARPS];

    const int b = blockIdx.x;
    const int tid = threadIdx.x;
    const int lane = tid & 31;
    const int wid = tid >> 5;
    const int gbase = b * NB;

    for (int i = tid; i < NB; i += FPS_THR) {
        const float* p = pos + (size_t)(gbase + i) * 3;
        sx[i] = p[0];
        sy[i] = p[1];
        sz[i] = p[2];
    }
    __syncthreads();

    u64 px2[PAIRS], py2[PAIRS], pz2[PAIRS];
    unsigned m[PPT];
#pragma unroll
    for (int j = 0; j < PAIRS; j++) {
        int i = tid * PPT + 2 * j;
        px2[j] = pk2(sx[i], sx[i + 1]);
        py2[j] = pk2(sy[i], sy[i + 1]);
        pz2[j] = pk2(sz[i], sz[i + 1]);
        m[2 * j] = 0x7f7fffffu;      // FLT_MAX bits
        m[2 * j + 1] = 0x7f7fffffu;
    }

    int widx = 0;  // idx[0] = 0 (deterministic start)
    for (int s = 0; s < M; s++) {
        const float cx = sx[widx], cy = sy[widx], cz = sz[widx];
        if (tid == 0) {
            float* o = out + ((size_t)b * M + s) * 3;
            o[0] = cx;
            o[1] = cy;
            o[2] = cz;
        }
        if (s == M - 1) break;
        const int par = s & 1;

        const u64 ncx = pk2(-cx, -cx);
        const u64 ncy = pk2(-cy, -cy);
        const u64 ncz = pk2(-cz, -cz);

        unsigned tmax = 0u;
#pragma unroll
        for (int j = 0; j < PAIRS; j++) {
            u64 dx = add2(px2[j], ncx);     // == px - cx per half
            u64 dy = add2(py2[j], ncy);
            u64 dz = add2(pz2[j], ncz);
            u64 t = mul2(dx, dx);
            t = fma2(dy, dy, t);
            t = fma2(dz, dz, t);
            unsigned d2a, d2b;
            upk2u(t, d2a, d2b);             // register aliasing, free
            unsigned ma = umin(m[2 * j], d2a);      // == fminf on nonneg
            unsigned mb = umin(m[2 * j + 1], d2b);
            m[2 * j] = ma;
            m[2 * j + 1] = mb;
            tmax = umax(tmax, ma);                  // == fmaxf on nonneg
            tmax = umax(tmax, mb);
        }

        // thread-local lowest j with m[j]==tmax (reverse scan: j=0 wins)
        int jbest = 0;
#pragma unroll
        for (int j = PPT - 1; j >= 0; j--)
            if (m[j] == tmax) jbest = j;
        const unsigned gidx = (unsigned)(tid * PPT + jbest);

        // warp argmax: (max value, lowest owner index)
        const unsigned wmax = __reduce_max_sync(0xffffffffu, tmax);
        const unsigned wcand = (tmax == wmax) ? gidx : 0xffffffffu;
        const unsigned wmin = __reduce_min_sync(0xffffffffu, wcand);
        if (lane == 0) {
            swd[par][wid] = wmax;
            swi[par][wid] = wmin;
        }
        __syncthreads();  // the ONLY barrier per step

        // all warps redundantly compute block argmax over the 16 entries
        const unsigned vd = (lane < FPS_WARPS) ? swd[par][lane] : 0u;
        const unsigned vi = (lane < FPS_WARPS) ? swi[par][lane] : 0xffffffffu;
        const unsigned gmax = __reduce_max_sync(0xffffffffu, vd);
        const unsigned gcand = (vd == gmax) ? vi : 0xffffffffu;
        widx = (int)__reduce_min_sync(0xffffffffu, gcand);
    }
}

// ---------------------------------------------------------------------------
// KNN, quarter-split: 512 threads, 16 warps. Warp w: centroid group
// cg = w>>2, quarter q = w&3; lane owns centroid c = cg*32+lane and scans
// points [q*2048, (q+1)*2048). Each quarter builds a (d2, idx)-lex-sorted
// top-16 (strict-< insert, ascending i => lower index first on ties).
// After sync, q==0 warps 4-way-merge with strict-< earliest-quarter
// comparator (quarter q indices all < quarter q+1 => == (d,idx)-lex order
// == lax.top_k semantics). Merge of partial lex-top-16s == full-scan
// top-16 exactly (each list fully real: 2048 pts >> 16; reads in bounds:
// sum of cursors = k <= 15).
// Per-point arithmetic replicates XLA emission exactly (R6/R13: 0.0):
//   pn, cn: square-and-reduce, plain mul/add (no contraction)
//   dot:    fma(cz,z, fma(cy,y, rn(cx*x)))
//   d2:     rn(cn - 2*dot) + pn
// Shared: float4 {x,y,z,|p|^2} -> 1x LDS.128 per point. smem = 192KB.
// ---------------------------------------------------------------------------
__global__ __launch_bounds__(KNN_THR, 1)
void knn_kernel(const float* __restrict__ pos, float* __restrict__ out) {
    extern __shared__ char smem_raw[];
    float4* shp = (float4*)smem_raw;                       // NB*16 = 128KB
    float* sd = (float*)(smem_raw + NB * sizeof(float4));  // 128*4*16 floats
    int* si = (int*)(sd + KNN_CPB * 4 * KNN);              // 128*4*16 ints

    const int bb = blockIdx.x;
    const int b = bb / KNN_BLKS_PER_BATCH;
    const int chunk = bb % KNN_BLKS_PER_BATCH;
    const int tid = threadIdx.x;
    const int lane = tid & 31;
    const int w = tid >> 5;
    const int cg = w >> 2;   // centroid group 0..3
    const int q = w & 3;     // quarter 0..3
    const int gbase = b * NB;

    for (int i = tid; i < NB; i += KNN_THR) {
        const float* p = pos + (size_t)(gbase + i) * 3;
        float xx = p[0], yy = p[1], zz = p[2];
        float pn = __fadd_rn(__fadd_rn(__fmul_rn(xx, xx), __fmul_rn(yy, yy)),
                             __fmul_rn(zz, zz));
        shp[i] = make_float4(xx, yy, zz, pn);
    }
    __syncthreads();

    const int c = cg * 32 + lane;            // centroid within block, 0..127
    const int mloc = chunk * KNN_CPB + c;    // centroid index within batch
    const float* cptr = out + ((size_t)b * M + mloc) * 3;
    const float cx = cptr[0], cy = cptr[1], cz = cptr[2];
    const float cn = __fadd_rn(__fadd_rn(__fmul_rn(cx, cx), __fmul_rn(cy, cy)),
                               __fmul_rn(cz, cz));

    float nd[KNN];
    int ni[KNN];
#pragma unroll
    for (int k = 0; k < KNN; k++) {
        nd[k] = FLT_MAX;
        ni[k] = 0;
    }

#define KNN_D2(P)                                                            \
    __fadd_rn(__fmaf_rn(-2.0f,                                               \
                        __fmaf_rn(cz, (P).z,                                 \
                                  __fmaf_rn(cy, (P).y, __fmul_rn(cx, (P).x))),\
                        cn),                                                 \
              (P).w)

#define KNN_INSERT(d2v, iv)                                                  \
    if ((d2v) < nd[KNN - 1]) {                                               \
        bool c2 = true;                                                      \
        _Pragma("unroll") for (int k = KNN - 1; k >= 1; k--) {               \
            bool c1 = (d2v) < nd[k - 1];                                     \
            float ndv = c1 ? nd[k - 1] : (c2 ? (d2v) : nd[k]);               \
            int niv = c1 ? ni[k - 1] : (c2 ? (iv) : ni[k]);                  \
            nd[k] = ndv;                                                     \
            ni[k] = niv;                                                     \
            c2 = c1;                                                         \
        }                                                                    \
        if (c2) {                                                            \
            nd[0] = (d2v);                                                   \
            ni[0] = (iv);                                                    \
        }                                                                    \
    }

    const int i0 = q * KNN_Q;
    for (int i = i0; i < i0 + KNN_Q; i += 4) {
        float4 p0 = shp[i + 0];
        float4 p1 = shp[i + 1];
        float4 p2 = shp[i + 2];
        float4 p3 = shp[i + 3];
        float d0 = KNN_D2(p0);
        float d1 = KNN_D2(p1);
        float d2 = KNN_D2(p2);
        float d3 = KNN_D2(p3);
        KNN_INSERT(d0, i + 0)
        KNN_INSERT(d1, i + 1)
        KNN_INSERT(d2, i + 2)
        KNN_INSERT(d3, i + 3)
    }
#undef KNN_D2
#undef KNN_INSERT

    // stash this quarter's sorted top-16
    {
        int off = (c * 4 + q) * KNN;
#pragma unroll
        for (int k = 0; k < KNN; k++) {
            sd[off + k] = nd[k];
            si[off + k] = ni[k];
        }
    }
    __syncthreads();

    // q==0 warps 4-way merge (strict <, earliest quarter wins ties ->
    // exact (d, idx)-lexicographic preference == lax.top_k)
    if (q == 0) {
        const int base = c * 4 * KNN;
        float* go = out + (size_t)BATCHES * M * 3 +
                    ((size_t)(b * M + mloc)) * KNN * 3;
        int p0 = 0, p1 = 0, p2 = 0, p3 = 0;
#pragma unroll
        for (int k = 0; k < KNN; k++) {
            float e0 = sd[base + 0 * KNN + p0];
            float e1 = sd[base + 1 * KNN + p1];
            float e2 = sd[base + 2 * KNN + p2];
            float e3 = sd[base + 3 * KNN + p3];
            int best = 0;
            float bd = e0;
            if (e1 < bd) { bd = e1; best = 1; }
            if (e2 < bd) { bd = e2; best = 2; }
            if (e3 < bd) { bd = e3; best = 3; }
            int pb = (best == 0) ? p0 : (best == 1) ? p1 : (best == 2) ? p2 : p3;
            int idx = si[base + best * KNN + pb];
            p0 += (best == 0);
            p1 += (best == 1);
            p2 += (best == 2);
            p3 += (best == 3);
            float4 p = shp[idx];
            go[k * 3 + 0] = p.x;
            go[k * 3 + 1] = p.y;
            go[k * 3 + 2] = p.z;
        }
    }
}

// ---------------------------------------------------------------------------
extern "C" void kernel_launch(void* const* d_in, const int* in_sizes, int n_in,
                              void* d_out, int out_size) {
    // metadata order: x (unused), pos, batch (block-constant, implied by i/NB)
    const float* pos = (const float*)d_in[1];
    float* out = (float*)d_out;

    const int knn_smem = NB * (int)sizeof(float4) +
                         KNN_CPB * 4 * KNN * (int)(sizeof(float) + sizeof(int));

    cudaFuncSetAttribute(fps_kernel, cudaFuncAttributeMaxDynamicSharedMemorySize,
                         3 * NB * (int)sizeof(float));
    cudaFuncSetAttribute(knn_kernel, cudaFuncAttributeMaxDynamicSharedMemorySize,
                         knn_smem);

    fps_kernel<<<BATCHES, FPS_THR, 3 * NB * sizeof(float)>>>(pos, out);
    knn_kernel<<<BATCHES * KNN_BLKS_PER_BATCH, KNN_THR, knn_smem>>>(pos, out);
}

// round 17
// speedup vs baseline: 1.2087x; 1.0536x over previous
#include <cuda_runtime.h>
#include <float.h>

// Problem constants
#define BATCHES 16
#define NB 8192
#define M 1024
#define KNN 16

// FPS kernel config
#define FPS_THR 512
#define PPT (NB / FPS_THR)        // 16 points per thread
#define PAIRS (PPT / 2)           // 8 f32x2 pairs per thread
#define FPS_WARPS (FPS_THR / 32)  // 16

// KNN kernel config: 256 threads; each centroid owned by a lane PAIR
// (two warps scan disjoint halves of the batch, then merge).
#define KNN_THR 256
#define KNN_CPB 128                        // centroids per block
#define KNN_BLKS_PER_BATCH (M / KNN_CPB)   // 8
#define KNN_HALF (NB / 2)                  // 4096 points per half

typedef unsigned long long u64;

// ---- f32x2 packed helpers (sm_103a; halves are exact independent rn ops) ----
__device__ __forceinline__ u64 pk2(float lo, float hi) {
    u64 r;
    asm("mov.b64 %0, {%1, %2};" : "=l"(r) : "f"(lo), "f"(hi));
    return r;
}
__device__ __forceinline__ void upk2u(u64 v, unsigned& lo, unsigned& hi) {
    asm("mov.b64 {%0, %1}, %2;" : "=r"(lo), "=r"(hi) : "l"(v));
}
__device__ __forceinline__ u64 add2(u64 a, u64 b) {
    u64 d;
    asm("add.rn.f32x2 %0, %1, %2;" : "=l"(d) : "l"(a), "l"(b));
    return d;
}
__device__ __forceinline__ u64 mul2(u64 a, u64 b) {
    u64 d;
    asm("mul.rn.f32x2 %0, %1, %2;" : "=l"(d) : "l"(a), "l"(b));
    return d;
}
__device__ __forceinline__ u64 fma2(u64 a, u64 b, u64 c) {
    u64 d;
    asm("fma.rn.f32x2 %0, %1, %2, %3;" : "=l"(d) : "l"(a), "l"(b), "l"(c));
    return d;
}

// ---------------------------------------------------------------------------
// FPS (R14-verified, ~517us): one block per batch; ONE barrier per step,
// atomic-free argmax. min_d2 as UINT BITS (d2 >= 0, init FLT_MAX bits:
// uint order == float order). Per step:
//   inner: packed f32x2 distance update (same rn sequence as reference),
//          umin/umax on bits.
//   thread: lowest j with m[j]==tmax (reverse scan, j=0 wins) -> gidx.
//   warp:  wmax = redux.max(tmax); cand = (tmax==wmax)?gidx:~0;
//          wmin = redux.min(cand).
//   lane0: store to DOUBLE-BUFFERED swd/swi[s&1][wid].   -- ONE barrier --
//   all warps: same redux pattern over the 16 entries -> (gmax, widx).
// Double-buffer race-freedom: buffer par read after barrier of step s; its
// next write is in step s+2, after barrier of step s+1. Tie-break = global
// lowest index (== jnp.argmax first-max). idx[0] = 0. (R14: rel_err 0.0.)
// ---------------------------------------------------------------------------
__global__ __launch_bounds__(FPS_THR, 1)
void fps_kernel(const float* __restrict__ pos, float* __restrict__ out) {
    extern __shared__ float sh[];
    float* sx = sh;
    float* sy = sh + NB;
    float* sz = sh + 2 * NB;
    __shared__ unsigned swd[2][FPS_WARPS];
    __shared__ unsigned swi[2][FPS_WARPS];

    const int b = blockIdx.x;
    const int tid = threadIdx.x;
    const int lane = tid & 31;
    const int wid = tid >> 5;
    const int gbase = b * NB;

    for (int i = tid; i < NB; i += FPS_THR) {
        const float* p = pos + (size_t)(gbase + i) * 3;
        sx[i] = p[0];
        sy[i] = p[1];
        sz[i] = p[2];
    }
    __syncthreads();

    u64 px2[PAIRS], py2[PAIRS], pz2[PAIRS];
    unsigned m[PPT];
#pragma unroll
    for (int j = 0; j < PAIRS; j++) {
        int i = tid * PPT + 2 * j;
        px2[j] = pk2(sx[i], sx[i + 1]);
        py2[j] = pk2(sy[i], sy[i + 1]);
        pz2[j] = pk2(sz[i], sz[i + 1]);
        m[2 * j] = 0x7f7fffffu;      // FLT_MAX bits
        m[2 * j + 1] = 0x7f7fffffu;
    }

    int widx = 0;  // idx[0] = 0 (deterministic start)
    for (int s = 0; s < M; s++) {
        const float cx = sx[widx], cy = sy[widx], cz = sz[widx];
        if (tid == 0) {
            float* o = out + ((size_t)b * M + s) * 3;
            o[0] = cx;
            o[1] = cy;
            o[2] = cz;
        }
        if (s == M - 1) break;
        const int par = s & 1;

        const u64 ncx = pk2(-cx, -cx);
        const u64 ncy = pk2(-cy, -cy);
        const u64 ncz = pk2(-cz, -cz);

        unsigned tmax = 0u;
#pragma unroll
        for (int j = 0; j < PAIRS; j++) {
            u64 dx = add2(px2[j], ncx);     // == px - cx per half
            u64 dy = add2(py2[j], ncy);
            u64 dz = add2(pz2[j], ncz);
            u64 t = mul2(dx, dx);
            t = fma2(dy, dy, t);
            t = fma2(dz, dz, t);
            unsigned d2a, d2b;
            upk2u(t, d2a, d2b);             // register aliasing, free
            unsigned ma = umin(m[2 * j], d2a);      // == fminf on nonneg
            unsigned mb = umin(m[2 * j + 1], d2b);
            m[2 * j] = ma;
            m[2 * j + 1] = mb;
            tmax = umax(tmax, ma);                  // == fmaxf on nonneg
            tmax = umax(tmax, mb);
        }

        // thread-local lowest j with m[j]==tmax (reverse scan: j=0 wins)
        int jbest = 0;
#pragma unroll
        for (int j = PPT - 1; j >= 0; j--)
            if (m[j] == tmax) jbest = j;
        const unsigned gidx = (unsigned)(tid * PPT + jbest);

        // warp argmax: (max value, lowest owner index)
        const unsigned wmax = __reduce_max_sync(0xffffffffu, tmax);
        const unsigned wcand = (tmax == wmax) ? gidx : 0xffffffffu;
        const unsigned wmin = __reduce_min_sync(0xffffffffu, wcand);
        if (lane == 0) {
            swd[par][wid] = wmax;
            swi[par][wid] = wmin;
        }
        __syncthreads();  // the ONLY barrier per step

        // all warps redundantly compute block argmax over the 16 entries
        const unsigned vd = (lane < FPS_WARPS) ? swd[par][lane] : 0u;
        const unsigned vi = (lane < FPS_WARPS) ? swi[par][lane] : 0xffffffffu;
        const unsigned gmax = __reduce_max_sync(0xffffffffu, vd);
        const unsigned gcand = (vd == gmax) ? vi : 0xffffffffu;
        widx = (int)__reduce_min_sync(0xffffffffu, gcand);
    }
}

// ---------------------------------------------------------------------------
// KNN (R13-verified, 298us): half-split, 256 threads. Warp w (0..7):
// centroid group cg = w>>1, half h = w&1; lane owns centroid c = cg*32+lane
// and scans points [h*4096, h*4096+4096). Each half builds a (d2, idx)-
// lexicographically sorted top-16 (strict-< insert, ascending i => lower
// index first on ties). After sync, the h=0 warp merges the two sorted
// lists with comparator dA<=dB (half-0 indices always lower => == (d,idx)-
// lex order == lax.top_k semantics). Merge of partial lex-top-16s ==
// full-scan top-16 exactly.
// Per-point arithmetic replicates XLA emission exactly (R6/R13: 0.0):
//   pn, cn: square-and-reduce, plain mul/add (no contraction)
//   dot:    fma(cz,z, fma(cy,y, rn(cx*x)))
//   d2:     rn(cn - 2*dot) + pn
// Shared: float4 {x,y,z,|p|^2} per point -> 1x LDS.128 per point.
// ---------------------------------------------------------------------------
__global__ __launch_bounds__(KNN_THR, 1)
void knn_kernel(const float* __restrict__ pos, float* __restrict__ out) {
    extern __shared__ char smem_raw[];
    float4* shp = (float4*)smem_raw;                       // NB*16 = 128KB
    float* sd = (float*)(smem_raw + NB * sizeof(float4));  // 128*32 floats
    int* si = (int*)(sd + KNN_CPB * 2 * KNN);              // 128*32 ints

    const int bb = blockIdx.x;
    const int b = bb / KNN_BLKS_PER_BATCH;
    const int chunk = bb % KNN_BLKS_PER_BATCH;
    const int tid = threadIdx.x;
    const int lane = tid & 31;
    const int w = tid >> 5;
    const int cg = w >> 1;   // centroid group 0..3
    const int h = w & 1;     // half 0/1
    const int gbase = b * NB;

    for (int i = tid; i < NB; i += KNN_THR) {
        const float* p = pos + (size_t)(gbase + i) * 3;
        float xx = p[0], yy = p[1], zz = p[2];
        float pn = __fadd_rn(__fadd_rn(__fmul_rn(xx, xx), __fmul_rn(yy, yy)),
                             __fmul_rn(zz, zz));
        shp[i] = make_float4(xx, yy, zz, pn);
    }
    __syncthreads();

    const int c = cg * 32 + lane;            // centroid within block, 0..127
    const int mloc = chunk * KNN_CPB + c;    // centroid index within batch
    const float* cptr = out + ((size_t)b * M + mloc) * 3;
    const float cx = cptr[0], cy = cptr[1], cz = cptr[2];
    const float cn = __fadd_rn(__fadd_rn(__fmul_rn(cx, cx), __fmul_rn(cy, cy)),
                               __fmul_rn(cz, cz));

    float nd[KNN];
    int ni[KNN];
#pragma unroll
    for (int k = 0; k < KNN; k++) {
        nd[k] = FLT_MAX;
        ni[k] = 0;
    }

#define KNN_D2(P)                                                            \
    __fadd_rn(__fmaf_rn(-2.0f,                                               \
                        __fmaf_rn(cz, (P).z,                                 \
                                  __fmaf_rn(cy, (P).y, __fmul_rn(cx, (P).x))),\
                        cn),                                                 \
              (P).w)

#define KNN_INSERT(d2v, iv)                                                  \
    if ((d2v) < nd[KNN - 1]) {                                               \
        bool c2 = true;                                                      \
        _Pragma("unroll") for (int k = KNN - 1; k >= 1; k--) {               \
            bool c1 = (d2v) < nd[k - 1];                                     \
            float ndv = c1 ? nd[k - 1] : (c2 ? (d2v) : nd[k]);               \
            int niv = c1 ? ni[k - 1] : (c2 ? (iv) : ni[k]);                  \
            nd[k] = ndv;                                                     \
            ni[k] = niv;                                                     \
            c2 = c1;                                                         \
        }                                                                    \
        if (c2) {                                                            \
            nd[0] = (d2v);                                                   \
            ni[0] = (iv);                                                    \
        }                                                                    \
    }

    const int i0 = h * KNN_HALF;
    for (int i = i0; i < i0 + KNN_HALF; i += 4) {
        float4 p0 = shp[i + 0];
        float4 p1 = shp[i + 1];
        float4 p2 = shp[i + 2];
        float4 p3 = shp[i + 3];
        float d0 = KNN_D2(p0);
        float d1 = KNN_D2(p1);
        float d2 = KNN_D2(p2);
        float d3 = KNN_D2(p3);
        KNN_INSERT(d0, i + 0)
        KNN_INSERT(d1, i + 1)
        KNN_INSERT(d2, i + 2)
        KNN_INSERT(d3, i + 3)
    }
#undef KNN_D2
#undef KNN_INSERT

    // stash this half's sorted top-16
    {
        int off = (c * 2 + h) * KNN;
#pragma unroll
        for (int k = 0; k < KNN; k++) {
            sd[off + k] = nd[k];
            si[off + k] = ni[k];
        }
    }
    __syncthreads();

    // h==0 warps merge the two sorted lists (dA<=dB: half-0 index always
    // lower, so <= implements exact (d, idx)-lexicographic preference)
    if (h == 0) {
        const float* dA = sd + (c * 2) * KNN;
        const int* iA = si + (c * 2) * KNN;
        const float* dB = sd + (c * 2 + 1) * KNN;
        const int* iB = si + (c * 2 + 1) * KNN;
        float* go = out + (size_t)BATCHES * M * 3 +
                    ((size_t)(b * M + mloc)) * KNN * 3;
        int a = 0, bcur = 0;
#pragma unroll
        for (int k = 0; k < KNN; k++) {
            float da = dA[a], db = dB[bcur];
            bool takeA = (da <= db);
            int idx = takeA ? iA[a] : iB[bcur];
            a += takeA ? 1 : 0;
            bcur += takeA ? 0 : 1;
            float4 p = shp[idx];
            go[k * 3 + 0] = p.x;
            go[k * 3 + 1] = p.y;
            go[k * 3 + 2] = p.z;
        }
    }
}

// ---------------------------------------------------------------------------
extern "C" void kernel_launch(void* const* d_in, const int* in_sizes, int n_in,
                              void* d_out, int out_size) {
    // metadata order: x (unused), pos, batch (block-constant, implied by i/NB)
    const float* pos = (const float*)d_in[1];
    float* out = (float*)d_out;

    const int knn_smem = NB * (int)sizeof(float4) +
                         KNN_CPB * 2 * KNN * (int)(sizeof(float) + sizeof(int));

    cudaFuncSetAttribute(fps_kernel, cudaFuncAttributeMaxDynamicSharedMemorySize,
                         3 * NB * (int)sizeof(float));
    cudaFuncSetAttribute(knn_kernel, cudaFuncAttributeMaxDynamicSharedMemorySize,
                         knn_smem);

    fps_kernel<<<BATCHES, FPS_THR, 3 * NB * sizeof(float)>>>(pos, out);
    knn_kernel<<<BATCHES * KNN_BLKS_PER_BATCH, KNN_THR, knn_smem>>>(pos, out);
}